// round 13
// baseline (speedup 1.0000x reference)
#include <cuda_runtime.h>
#include <math.h>

typedef unsigned long long ull;

#define T_   64
#define B_   32
#define H_   256
#define G_   768
#define DD_  256
#define DIN_ 4096
#define DOUT_ 942
#define M_   (T_*B_)
#define HSTR 260
#define BH_  (B_*H_)
#define BG_  (B_*G_)

__device__ float g_day [M_*DD_];
__device__ float g_gif [M_*G_];
__device__ float g_gir [M_*G_];
__device__ float g_hA  [65*BH_];
__device__ float g_hB  [65*BH_];
__device__ float g_fwd [T_*BH_];
__device__ float g_rev [T_*T_*BH_];
__device__ float g_scrp[8*T_*T_*B_];
__device__ float g_scfp[8*T_*B_];
__device__ float g_sc  [T_*T_*B_];
__device__ float g_ht  [M_*4*H_];
__device__ float g_hto [M_*DD_];

#define ZHA (65*BH_)

__device__ __forceinline__ ull splat2(float x){ull r;asm("mov.b64 %0,{%1,%1};":"=l"(r):"f"(x));return r;}
__device__ __forceinline__ void fma2(ull&c,ull a,ull b){asm("fma.rn.f32x2 %0,%1,%2,%0;":"+l"(c):"l"(a),"l"(b));}
__device__ __forceinline__ float2 unpack2(ull v){float2 r;asm("mov.b64 {%0,%1},%2;":"=f"(r.x),"=f"(r.y):"l"(v));return r;}
__device__ __forceinline__ float ex2f_(float x){float y;asm("ex2.approx.f32 %0,%1;":"=f"(y):"f"(x));return y;}
__device__ __forceinline__ float rcpf_(float x){float y;asm("rcp.approx.f32 %0,%1;":"=f"(y):"f"(x));return y;}
__device__ __forceinline__ float sigm(float x){return rcpf_(1.f+ex2f_(-1.4426950408889634f*x));}
__device__ __forceinline__ float tanh_(float x){return fmaf(-2.f,rcpf_(1.f+ex2f_(2.8853900817779268f*x)),1.f);}

__global__ void zero_k() {
    for (int j = blockIdx.x*256 + threadIdx.x; j < ZHA; j += gridDim.x*256)
        g_hA[j] = 0.f;
}

// ---------------- GEMM: C[M,N] = A[M,K] @ B[N,K]^T + bias ----------------
template<bool SIG>
__device__ __forceinline__ void gemm_body(
    const float* __restrict__ A, const float* __restrict__ Bm,
    const float* __restrict__ bias, float* __restrict__ C,
    int N, int K, int m0, int n0, float* As, float* Bs)
{
    const int tid = threadIdx.x, lane = tid & 31, w = tid >> 5;
    const int arow = tid >> 3, ak = (tid & 7)*4;
    const int bcol = tid >> 2, bk = (tid & 3)*4;
    const bool bvalid = (n0 + bcol) < N;
    const float* Aptr = A + (size_t)(m0+arow)*K + ak;
    const float* Bptr = Bm + (size_t)(n0+bcol)*K + bk;
    float4 pa = *(const float4*)Aptr;
    float4 pb0 = bvalid ? *(const float4*)(Bptr) : make_float4(0,0,0,0);
    float4 pb1 = bvalid ? *(const float4*)(Bptr+16) : make_float4(0,0,0,0);
    ull acc[4] = {0,0,0,0};
    for (int k0 = 0; k0 < K; k0 += 32) {
        __syncthreads();
        As[(ak+0)*33+arow]=pa.x; As[(ak+1)*33+arow]=pa.y;
        As[(ak+2)*33+arow]=pa.z; As[(ak+3)*33+arow]=pa.w;
        Bs[(bk+0)*68+bcol]=pb0.x; Bs[(bk+1)*68+bcol]=pb0.y;
        Bs[(bk+2)*68+bcol]=pb0.z; Bs[(bk+3)*68+bcol]=pb0.w;
        Bs[(bk+16)*68+bcol]=pb1.x; Bs[(bk+17)*68+bcol]=pb1.y;
        Bs[(bk+18)*68+bcol]=pb1.z; Bs[(bk+19)*68+bcol]=pb1.w;
        __syncthreads();
        if (k0+32 < K) {
            pa = *(const float4*)(Aptr+k0+32);
            if (bvalid) { pb0 = *(const float4*)(Bptr+k0+32); pb1 = *(const float4*)(Bptr+k0+48); }
        }
#pragma unroll 8
        for (int kk = 0; kk < 32; kk++) {
            ull av = splat2(As[kk*33+lane]);
            ulonglong2 L0 = *(const ulonglong2*)&Bs[kk*68+(w<<3)];
            ulonglong2 L1 = *(const ulonglong2*)&Bs[kk*68+(w<<3)+4];
            fma2(acc[0],av,L0.x); fma2(acc[1],av,L0.y);
            fma2(acc[2],av,L1.x); fma2(acc[3],av,L1.y);
        }
    }
    const int row = m0 + lane;
#pragma unroll
    for (int p = 0; p < 4; p++) {
        int col = n0 + (w<<3) + 2*p;
        float2 v = unpack2(acc[p]);
        if (col+1 < N) {
            v.x += bias[col]; v.y += bias[col+1];
            if (SIG) { v.x = sigm(v.x); v.y = sigm(v.y); }
            *(float2*)(C + (size_t)row*N + col) = v;
        } else if (col < N) {
            v.x += bias[col]; if (SIG) v.x = sigm(v.x);
            C[(size_t)row*N + col] = v.x;
        }
    }
}

template<bool SIG>
__global__ __launch_bounds__(256) void gemm_v2(
    const float* __restrict__ A, const float* __restrict__ Bm,
    const float* __restrict__ bias, float* __restrict__ C, int N, int K)
{
    __shared__ float As[32*33]; __shared__ float Bs[32*68];
    gemm_body<SIG>(A, Bm, bias, C, N, K, blockIdx.y*32, blockIdx.x*64, As, Bs);
}

__global__ __launch_bounds__(256) void gi_fused(
    const float* __restrict__ Wih_f, const float* __restrict__ bih_f,
    const float* __restrict__ Wih_r, const float* __restrict__ bih_r)
{
    __shared__ float As[32*33]; __shared__ float Bs[32*68];
    const bool r = (blockIdx.z == 1);
    gemm_body<false>(g_day, r?Wih_r:Wih_f, r?bih_r:bih_f, r?g_gir:g_gif,
                     G_, DD_, blockIdx.y*32, blockIdx.x*64, As, Bs);
}

// queue resolve: chain id 0..63 = rev i (len i+1), 64 = fwd (len 64), -1 = none
__device__ __forceinline__ void resolve(int q0, int q1, int s, int& c, int& ls) {
    int l0 = (q0 == 64) ? 64 : (q0 + 1);
    if (q0 >= 0 && s < l0) { c = q0; ls = s; return; }
    if (q1 >= 0) {
        int l1 = q1 + 1;
        if (s < l0 + l1) { c = q1; ls = s - l0; return; }
    }
    c = -1; ls = 0;
}

// ---------------- one-wave slot-queue recurrence, makespan 66 ----------------
// 136 blocks = 17 clusters x 8 chunks, all co-resident.
// g0: A=[fwd] (64 steps). Rev queues q=0..31 over g1..g16 (A=q 2g-2, B=q 2g-1):
//   q<=30: chains (q+1, 63-q)  -> lengths (q+2)+(64-q)=66
//   q==31: chains (0, 32)      -> lengths 1+33=34
__global__ __launch_bounds__(256) __cluster_dims__(8,1,1)
void chain_rnn(const float* __restrict__ Whh_f, const float* __restrict__ Whh_r,
               const float* __restrict__ bhh_f, const float* __restrict__ bhh_r,
               const float* __restrict__ attn_w)
{
    extern __shared__ float sm[];
    float* WS  = sm;                 // 96x256 = 24576
    float* HSA = sm + 24576;         // 32*HSTR
    float* HSB = HSA + 32*HSTR;
    float* SBA = HSB + 32*HSTR;      // 256
    float* SBB = SBA + 256;          // 256

    const int tid = threadIdx.x, lane = tid & 31, w = tid >> 5;
    const int grp = blockIdx.x >> 3, chunk = blockIdx.x & 7, c0 = chunk*32;
    const bool isf = (grp == 0);

    // slot queues (g0 + 32 rev queues cover all 65 chains exactly once)
    int a0=-1, a1=-1, b0=-1, b1=-1;
    if (grp == 0) { a0 = 64; }
    else {
        int qA = 2*(grp - 1) - 2 + 2;   // = 2*grp - 2... keep simple below
        qA = 2*grp - 2;                  // g=1 -> 0, g=16 -> 30 (all <= 30)
        int qB = qA + 1;                 // g=1 -> 1, g=16 -> 31
        a0 = qA + 1;  a1 = 63 - qA;
        if (qB <= 30) { b0 = qB + 1; b1 = 63 - qB; }
        else          { b0 = 0;      b1 = 32;      }   // qB == 31
    }

    const float* Wg   = isf ? Whh_f : Whh_r;
    const float* bias = isf ? bhh_f : bhh_r;

    // stage W slice once (gate rows r[0..31], z[32..63], n[64..95])
    for (int idx = tid; idx < 96*64; idx += 256) {
        int row = idx % 96, k4 = (idx/96)*4;
        int grow = (row>>5)*256 + c0 + (row&31);
        float4 v = *(const float4*)(Wg + (size_t)grow*256 + k4);
        WS[(k4+0)*96+row]=v.x; WS[(k4+1)*96+row]=v.y;
        WS[(k4+2)*96+row]=v.z; WS[(k4+3)*96+row]=v.w;
    }

    const int hc = w<<2, hcg = c0 + hc;
    const float4 br = *(const float4*)(bias + hcg);
    const float4 bz = *(const float4*)(bias + 256 + hcg);
    const float4 bn = *(const float4*)(bias + 512 + hcg);
    const float4 wvA = *(const float4*)(attn_w + (isf?0:256) + hcg);
    const float4 wvB = *(const float4*)(attn_w + 256 + hcg);

    const int srow = tid >> 3, skb = (tid & 7)*4;
    __syncthreads();

    const int nsteps = isf ? 64 : 66;
    for (int s = 0; s < nsteps; s++) {
        int cA, lsA, cB, lsB;
        resolve(a0, a1, s, cA, lsA);
        resolve(b0, b1, s, cB, lsB);
        const bool actA = (cA >= 0);
        const bool actB = (cB >= 0);

        float* hbaseA_A = g_hA + (size_t)(actA ? cA : 0)*BH_;
        float* hbaseA_B = g_hB + (size_t)(actA ? cA : 0)*BH_;
        float* hbaseB_A = g_hA + (size_t)(actB ? cB : 0)*BH_;
        float* hbaseB_B = g_hB + (size_t)(actB ? cB : 0)*BH_;
        float* hsrcA = (lsA&1) ? hbaseA_B : hbaseA_A;
        float* hdstA = (lsA&1) ? hbaseA_A : hbaseA_B;
        float* hsrcB = (lsB&1) ? hbaseB_B : hbaseB_A;
        float* hdstB = (lsB&1) ? hbaseB_A : hbaseB_B;

        // stage h (32x256) via float4, conflict-free
        if (actA) {
            const float* src = hsrcA + srow*256 + skb;
            float* d = HSA + srow*HSTR + skb;
#pragma unroll
            for (int q = 0; q < 8; q++) *(float4*)(d+q*32) = __ldcg((const float4*)(src+q*32));
        }
        if (actB) {
            const float* sb = hsrcB + srow*256 + skb;
            float* db = HSB + srow*HSTR + skb;
#pragma unroll
            for (int q = 0; q < 8; q++) *(float4*)(db+q*32) = __ldcg((const float4*)(sb+q*32));
        }
        __syncthreads();

        float4 grA, gzA, gnA, grB, gzB, gnB;
        if (actA) {
            const float* giA = ((cA==64) ? (g_gif + (size_t)lsA*BG_)
                                         : (g_gir + (size_t)(cA-lsA)*BG_)) + (size_t)lane*G_ + hcg;
            grA = *(const float4*)giA; gzA = *(const float4*)(giA+256); gnA = *(const float4*)(giA+512);
        }
        if (actB) {
            const float* giB = g_gir + (size_t)(cB-lsB)*BG_ + (size_t)lane*G_ + hcg;
            grB = *(const float4*)giB; gzB = *(const float4*)(giB+256); gnB = *(const float4*)(giB+512);
        }

        ull aA[6] = {0,0,0,0,0,0}, aB[6] = {0,0,0,0,0,0};
        const float* wk = WS + hc;
        const float* hkA = HSA + lane*HSTR;
        const float* hkB = HSB + lane*HSTR;
        if (actA && actB) {
#pragma unroll 4
            for (int kq = 0; kq < 64; kq++) {
                float4 hA4 = *(const float4*)(hkA + kq*4);
                float4 hB4 = *(const float4*)(hkB + kq*4);
                const float* fA = (const float*)&hA4;
                const float* fB = (const float*)&hB4;
#pragma unroll
                for (int j = 0; j < 4; j++) {
                    const float* wp = wk + (kq*4+j)*96;
                    ulonglong2 rr = *(const ulonglong2*)(wp);
                    ulonglong2 zz = *(const ulonglong2*)(wp+32);
                    ulonglong2 nn = *(const ulonglong2*)(wp+64);
                    ull avA = splat2(fA[j]), avB = splat2(fB[j]);
                    fma2(aA[0],avA,rr.x); fma2(aA[1],avA,rr.y);
                    fma2(aA[2],avA,zz.x); fma2(aA[3],avA,zz.y);
                    fma2(aA[4],avA,nn.x); fma2(aA[5],avA,nn.y);
                    fma2(aB[0],avB,rr.x); fma2(aB[1],avB,rr.y);
                    fma2(aB[2],avB,zz.x); fma2(aB[3],avB,zz.y);
                    fma2(aB[4],avB,nn.x); fma2(aB[5],avB,nn.y);
                }
            }
        } else if (actA) {
#pragma unroll 4
            for (int kq = 0; kq < 64; kq++) {
                float4 hA4 = *(const float4*)(hkA + kq*4);
                const float* fA = (const float*)&hA4;
#pragma unroll
                for (int j = 0; j < 4; j++) {
                    const float* wp = wk + (kq*4+j)*96;
                    ulonglong2 rr = *(const ulonglong2*)(wp);
                    ulonglong2 zz = *(const ulonglong2*)(wp+32);
                    ulonglong2 nn = *(const ulonglong2*)(wp+64);
                    ull avA = splat2(fA[j]);
                    fma2(aA[0],avA,rr.x); fma2(aA[1],avA,rr.y);
                    fma2(aA[2],avA,zz.x); fma2(aA[3],avA,zz.y);
                    fma2(aA[4],avA,nn.x); fma2(aA[5],avA,nn.y);
                }
            }
        }

        // pointwise A
        if (actA) {
            float2 r01=unpack2(aA[0]), r23=unpack2(aA[1]);
            float2 z01=unpack2(aA[2]), z23=unpack2(aA[3]);
            float2 n01=unpack2(aA[4]), n23=unpack2(aA[5]);
            const float* hp_ = hkA + hcg;
            float r0=sigm(grA.x+r01.x+br.x), r1=sigm(grA.y+r01.y+br.y);
            float r2=sigm(grA.z+r23.x+br.z), r3=sigm(grA.w+r23.y+br.w);
            float z0=sigm(gzA.x+z01.x+bz.x), z1=sigm(gzA.y+z01.y+bz.y);
            float z2=sigm(gzA.z+z23.x+bz.z), z3=sigm(gzA.w+z23.y+bz.w);
            float n0=tanh_(gnA.x+r0*(n01.x+bn.x)), n1=tanh_(gnA.y+r1*(n01.y+bn.y));
            float n2=tanh_(gnA.z+r2*(n23.x+bn.z)), n3=tanh_(gnA.w+r3*(n23.y+bn.w));
            float4 hv;
            hv.x=(1.f-z0)*n0+z0*hp_[0]; hv.y=(1.f-z1)*n1+z1*hp_[1];
            hv.z=(1.f-z2)*n2+z2*hp_[2]; hv.w=(1.f-z3)*n3+z3*hp_[3];
            __stcg((float4*)(hdstA + lane*256 + hcg), hv);
            float* outp = (cA==64) ? (g_fwd + (size_t)lsA*BH_)
                                   : (g_rev + ((size_t)cA*64 + lsA)*BH_);
            *(float4*)(outp + lane*256 + hcg) = hv;
            SBA[w*32+lane] = hv.x*wvA.x + hv.y*wvA.y + hv.z*wvA.z + hv.w*wvA.w;
        }
        // pointwise B
        if (actB) {
            float2 r01=unpack2(aB[0]), r23=unpack2(aB[1]);
            float2 z01=unpack2(aB[2]), z23=unpack2(aB[3]);
            float2 n01=unpack2(aB[4]), n23=unpack2(aB[5]);
            const float* hp_ = hkB + hcg;
            float r0=sigm(grB.x+r01.x+br.x), r1=sigm(grB.y+r01.y+br.y);
            float r2=sigm(grB.z+r23.x+br.z), r3=sigm(grB.w+r23.y+br.w);
            float z0=sigm(gzB.x+z01.x+bz.x), z1=sigm(gzB.y+z01.y+bz.y);
            float z2=sigm(gzB.z+z23.x+bz.z), z3=sigm(gzB.w+z23.y+bz.w);
            float n0=tanh_(gnB.x+r0*(n01.x+bn.x)), n1=tanh_(gnB.y+r1*(n01.y+bn.y));
            float n2=tanh_(gnB.z+r2*(n23.x+bn.z)), n3=tanh_(gnB.w+r3*(n23.y+bn.w));
            float4 hv;
            hv.x=(1.f-z0)*n0+z0*hp_[0]; hv.y=(1.f-z1)*n1+z1*hp_[1];
            hv.z=(1.f-z2)*n2+z2*hp_[2]; hv.w=(1.f-z3)*n3+z3*hp_[3];
            __stcg((float4*)(hdstB + lane*256 + hcg), hv);
            *(float4*)(g_rev + ((size_t)cB*64 + lsB)*BH_ + lane*256 + hcg) = hv;
            SBB[w*32+lane] = hv.x*wvB.x + hv.y*wvB.y + hv.z*wvB.z + hv.w*wvB.w;
        }
        __syncthreads();
        if (w == 0 && actA) {
            float v = 0.f;
#pragma unroll
            for (int q = 0; q < 8; q++) v += SBA[q*32+lane];
            if (cA==64) g_scfp[(chunk*64+lsA)*32+lane] = v;
            else        g_scrp[(((size_t)chunk*64+cA)*64+lsA)*32+lane] = v;
        } else if (w == 1 && actB) {
            float v = 0.f;
#pragma unroll
            for (int q = 0; q < 8; q++) v += SBB[q*32+lane];
            g_scrp[(((size_t)chunk*64+cB)*64+lsB)*32+lane] = v;
        }
        if (s != nsteps-1) {
            asm volatile("barrier.cluster.arrive.aligned;" ::: "memory");
            asm volatile("barrier.cluster.wait.aligned;"   ::: "memory");
        }
    }
}

__global__ __launch_bounds__(256) void combine_softmax(const float* __restrict__ attn_b) {
    const int i = blockIdx.x;
    __shared__ float sc[T_*B_];
    const float ab = attn_b[0];
    for (int idx = threadIdx.x; idx < (i+1)*32; idx += 256) {
        int t = idx >> 5, b = idx & 31;
        float v = ab;
#pragma unroll
        for (int c = 0; c < 8; c++) {
            v += g_scrp[(((size_t)c*64+i)*64+t)*32+b];
            v += g_scfp[(c*64+t)*32+b];
        }
        sc[t*32+b] = v;
    }
    __syncthreads();
    if (threadIdx.x < 32) {
        const int b = threadIdx.x;
        float m = -1e30f;
        for (int t = 0; t <= i; t++) m = fmaxf(m, sc[t*32+b]);
        float ssum = 0.f;
        for (int t = 0; t <= i; t++) {
            float e = ex2f_(1.4426950408889634f*(sc[t*32+b]-m));
            sc[t*32+b] = e; ssum += e;
        }
        float inv = 1.f/ssum;
        for (int t = 0; t <= i; t++) g_sc[(i*64+t)*32+b] = sc[t*32+b]*inv;
    }
}

__global__ __launch_bounds__(256) void context_k() {
    const int i = blockIdx.x, bg = blockIdx.y;
    const int h = threadIdx.x;
    float accf[8], accr[8];
#pragma unroll
    for (int j = 0; j < 8; j++) { accf[j]=0.f; accr[j]=0.f; }
    for (int t = 0; t <= i; t++) {
        const float* al = g_sc + (i*64+t)*32 + bg*8;
        const float* fr = g_fwd + ((size_t)(t*32+bg*8))*256 + h;
        const float* rr = g_rev + ((size_t)((i*64+t)*32+bg*8))*256 + h;
#pragma unroll
        for (int j = 0; j < 8; j++) {
            float a = al[j];
            accf[j] += a*fr[(size_t)j*256];
            accr[j] += a*rr[(size_t)j*256];
        }
    }
    float inv = 1.f/(float)(i+1);
#pragma unroll
    for (int j = 0; j < 8; j++) {
        int b = bg*8+j;
        size_t row = (size_t)(i*32+b);
        g_ht[row*1024 + h]       = accf[j]*inv;
        g_ht[row*1024 + 256 + h] = accr[j]*inv;
        g_ht[row*1024 + 512 + h] = g_fwd[((size_t)(i*32+b))*256 + h];
        g_ht[row*1024 + 768 + h] = g_rev[((size_t)((i*64+i)*32+b))*256 + h];
    }
}

extern "C" void kernel_launch(void* const* d_in, const int* in_sizes, int n_in,
                              void* d_out, int out_size)
{
    const float* x      = (const float*)d_in[0];
    const float* W_emb  = (const float*)d_in[1];
    const float* b_emb  = (const float*)d_in[2];
    const float* Wih_f  = (const float*)d_in[3];
    const float* Whh_f  = (const float*)d_in[4];
    const float* bih_f  = (const float*)d_in[5];
    const float* bhh_f  = (const float*)d_in[6];
    const float* Wih_r  = (const float*)d_in[7];
    const float* Whh_r  = (const float*)d_in[8];
    const float* bih_r  = (const float*)d_in[9];
    const float* bhh_r  = (const float*)d_in[10];
    const float* attn_w = (const float*)d_in[11];
    const float* attn_b = (const float*)d_in[12];
    const float* W_ao   = (const float*)d_in[13];
    const float* b_ao   = (const float*)d_in[14];
    const float* W_o    = (const float*)d_in[15];
    const float* b_o    = (const float*)d_in[16];
    float* out = (float*)d_out;

    void *p_day, *p_ht, *p_hto;
    cudaGetSymbolAddress(&p_day, g_day);
    cudaGetSymbolAddress(&p_ht,  g_ht);
    cudaGetSymbolAddress(&p_hto, g_hto);

    const int RNN_SMEM = (24576 + 2*32*HSTR + 512) * 4;  // 166912 B
    cudaFuncSetAttribute(chain_rnn, cudaFuncAttributeMaxDynamicSharedMemorySize, RNN_SMEM);

    zero_k<<<256, 256>>>();                                                   // 0
    gemm_v2<false><<<dim3(4, 64), 256>>>(x, W_emb, b_emb, (float*)p_day, DD_, DIN_);  // 1
    gi_fused<<<dim3(12, 64, 2), 256>>>(Wih_f, bih_f, Wih_r, bih_r);           // 2
    chain_rnn<<<136, 256, RNN_SMEM>>>(Whh_f, Whh_r, bhh_f, bhh_r, attn_w);    // 3 (profiled)
    combine_softmax<<<64, 256>>>(attn_b);                                     // 4
    context_k<<<dim3(64, 4), 256>>>();                                        // 5
    gemm_v2<false><<<dim3(4, 64), 256>>>((const float*)p_ht, W_ao, b_ao, (float*)p_hto, DD_, 4*H_); // 6
    gemm_v2<true><<<dim3(15, 64), 256>>>((const float*)p_hto, W_o, b_o, out, DOUT_, DD_);           // 7
}

// round 14
// speedup vs baseline: 1.4172x; 1.4172x over previous
#include <cuda_runtime.h>
#include <math.h>

typedef unsigned long long ull;

#define T_   64
#define B_   32
#define H_   256
#define G_   768
#define DD_  256
#define DIN_ 4096
#define DOUT_ 942
#define M_   (T_*B_)
#define HSTR 260

__device__ float g_day [M_*DD_];
__device__ float g_gif [M_*G_];
__device__ float g_gir [M_*G_];
__device__ float g_hA  [65*B_*H_];
__device__ float g_hB  [65*B_*H_];
__device__ float g_fwd [T_*B_*H_];
__device__ float g_rev [T_*T_*B_*H_];
__device__ float g_scrp[8*T_*T_*B_];
__device__ float g_scfp[8*T_*B_];
__device__ float g_sc  [T_*T_*B_];
__device__ float g_ht  [M_*4*H_];
__device__ float g_hto [M_*DD_];

#define ZHA (65*B_*H_)
#define ZRP (8*T_*T_*B_)
#define ZFP (8*T_*B_)
#define ZTOT (ZHA+ZRP+ZFP)

__device__ __forceinline__ ull splat2(float x){ull r;asm("mov.b64 %0,{%1,%1};":"=l"(r):"f"(x));return r;}
__device__ __forceinline__ void fma2(ull&c,ull a,ull b){asm("fma.rn.f32x2 %0,%1,%2,%0;":"+l"(c):"l"(a),"l"(b));}
__device__ __forceinline__ float2 unpack2(ull v){float2 r;asm("mov.b64 {%0,%1},%2;":"=f"(r.x),"=f"(r.y):"l"(v));return r;}
__device__ __forceinline__ float ex2f_(float x){float y;asm("ex2.approx.f32 %0,%1;":"=f"(y):"f"(x));return y;}
__device__ __forceinline__ float rcpf_(float x){float y;asm("rcp.approx.f32 %0,%1;":"=f"(y):"f"(x));return y;}
__device__ __forceinline__ float sigm(float x){return rcpf_(1.f+ex2f_(-1.4426950408889634f*x));}
__device__ __forceinline__ float tanh_(float x){return fmaf(-2.f,rcpf_(1.f+ex2f_(2.8853900817779268f*x)),1.f);}

__global__ void zero_k() {
    for (int j = blockIdx.x*256 + threadIdx.x; j < ZTOT; j += gridDim.x*256) {
        if (j < ZHA) g_hA[j] = 0.f;
        else if (j < ZHA+ZRP) g_scrp[j-ZHA] = 0.f;
        else g_scfp[j-ZHA-ZRP] = 0.f;
    }
}

// ------- GEMM v3: 64x64 tile, 256 thr, 4x4 frag: C = A[M,K] @ B[N,K]^T + bias
template<bool SIG>
__device__ __forceinline__ void gemm3_body(
    const float* __restrict__ A, const float* __restrict__ Bm,
    const float* __restrict__ bias, float* __restrict__ C,
    int N, int K, int m0, int n0, float* As, float* Bs)
{
    const int tid = threadIdx.x;
    const int ty = tid >> 4, tx = tid & 15;
    const int lrow = tid & 63, lkb = (tid >> 6) * 4;   // loader: row, k-quad
    const bool bval = (n0 + lrow) < N;
    const float* Ap = A + (size_t)(m0 + lrow)*K + lkb;
    const float* Bp = Bm + (size_t)(n0 + lrow)*K + lkb;

    float4 pa0 = *(const float4*)Ap;
    float4 pa1 = *(const float4*)(Ap + 16);
    float4 pb0 = bval ? *(const float4*)Bp        : make_float4(0,0,0,0);
    float4 pb1 = bval ? *(const float4*)(Bp + 16) : make_float4(0,0,0,0);

    ull acc[4][2];
#pragma unroll
    for (int r = 0; r < 4; r++) { acc[r][0] = 0ull; acc[r][1] = 0ull; }

    for (int k0 = 0; k0 < K; k0 += 32) {
        __syncthreads();
        {
            const float* fa0 = (const float*)&pa0;
            const float* fa1 = (const float*)&pa1;
            const float* fb0 = (const float*)&pb0;
            const float* fb1 = (const float*)&pb1;
#pragma unroll
            for (int j = 0; j < 4; j++) {
                As[(lkb+j)*68 + lrow]      = fa0[j];
                As[(lkb+16+j)*68 + lrow]   = fa1[j];
                Bs[(lkb+j)*68 + lrow]      = fb0[j];
                Bs[(lkb+16+j)*68 + lrow]   = fb1[j];
            }
        }
        __syncthreads();
        if (k0 + 32 < K) {
            pa0 = *(const float4*)(Ap + k0 + 32);
            pa1 = *(const float4*)(Ap + k0 + 48);
            if (bval) {
                pb0 = *(const float4*)(Bp + k0 + 32);
                pb1 = *(const float4*)(Bp + k0 + 48);
            }
        }
#pragma unroll 8
        for (int kk = 0; kk < 32; kk++) {
            float4 a4 = *(const float4*)&As[kk*68 + ty*4];
            ulonglong2 b2 = *(const ulonglong2*)&Bs[kk*68 + tx*4];
            fma2(acc[0][0], splat2(a4.x), b2.x); fma2(acc[0][1], splat2(a4.x), b2.y);
            fma2(acc[1][0], splat2(a4.y), b2.x); fma2(acc[1][1], splat2(a4.y), b2.y);
            fma2(acc[2][0], splat2(a4.z), b2.x); fma2(acc[2][1], splat2(a4.z), b2.y);
            fma2(acc[3][0], splat2(a4.w), b2.x); fma2(acc[3][1], splat2(a4.w), b2.y);
        }
    }

#pragma unroll
    for (int r = 0; r < 4; r++) {
        const int row = m0 + ty*4 + r;
#pragma unroll
        for (int p = 0; p < 2; p++) {
            int col = n0 + tx*4 + 2*p;
            float2 v = unpack2(acc[r][p]);
            if (col + 1 < N) {
                v.x += bias[col]; v.y += bias[col+1];
                if (SIG) { v.x = sigm(v.x); v.y = sigm(v.y); }
                *(float2*)(C + (size_t)row*N + col) = v;
            } else if (col < N) {
                v.x += bias[col]; if (SIG) v.x = sigm(v.x);
                C[(size_t)row*N + col] = v.x;
            }
        }
    }
}

template<bool SIG>
__global__ __launch_bounds__(256) void gemm_v3(
    const float* __restrict__ A, const float* __restrict__ Bm,
    const float* __restrict__ bias, float* __restrict__ C, int N, int K)
{
    __shared__ float As[32*68]; __shared__ float Bs[32*68];
    gemm3_body<SIG>(A, Bm, bias, C, N, K, blockIdx.y*64, blockIdx.x*64, As, Bs);
}

__global__ __launch_bounds__(256) void gi_fused(
    const float* __restrict__ Wih_f, const float* __restrict__ bih_f,
    const float* __restrict__ Wih_r, const float* __restrict__ bih_r)
{
    __shared__ float As[32*68]; __shared__ float Bs[32*68];
    const bool r = (blockIdx.z == 1);
    gemm3_body<false>(g_day, r?Wih_r:Wih_f, r?bih_r:bih_f, r?g_gir:g_gif,
                      G_, DD_, blockIdx.y*64, blockIdx.x*64, As, Bs);
}

// ---------------- paired-chain cluster recurrence (R8, verbatim) ------------
// 264 blocks = 33 groups x 8 chunks, cluster 8. group 0: fwd chain alone
// (slot 64). group g>=1: rev chains iA=65-2g (63..1) and iB=64-2g (62..0).
__global__ __launch_bounds__(256) __cluster_dims__(8,1,1)
void chain_rnn(const float* __restrict__ Whh_f, const float* __restrict__ Whh_r,
               const float* __restrict__ bhh_f, const float* __restrict__ bhh_r,
               const float* __restrict__ attn_w)
{
    extern __shared__ float sm[];
    float* WS  = sm;                 // 96x256 = 24576
    float* HSA = sm + 24576;         // 32*HSTR
    float* HSB = HSA + 32*HSTR;
    float* SBA = HSB + 32*HSTR;      // 256
    float* SBB = SBA + 256;          // 256

    const int tid = threadIdx.x, lane = tid & 31, w = tid >> 5;
    const int grp = blockIdx.x >> 3, chunk = blockIdx.x & 7, c0 = chunk*32;
    const bool isf = (grp == 0);
    const int iA = 65 - 2*grp;            // 63..1 for grp 1..32
    const int iB = 64 - 2*grp;            // 62..0
    const int lenA = isf ? 64 : (iA + 1);
    const int lenB = iB + 1;
    const int slotA = isf ? 64 : iA;

    const float* Wg   = isf ? Whh_f : Whh_r;
    const float* bias = isf ? bhh_f : bhh_r;

    for (int idx = tid; idx < 96*64; idx += 256) {
        int row = idx % 96, k4 = (idx/96)*4;
        int grow = (row>>5)*256 + c0 + (row&31);
        float4 v = *(const float4*)(Wg + (size_t)grow*256 + k4);
        WS[(k4+0)*96+row]=v.x; WS[(k4+1)*96+row]=v.y;
        WS[(k4+2)*96+row]=v.z; WS[(k4+3)*96+row]=v.w;
    }

    const int hc = w<<2, hcg = c0 + hc;
    const float4 br = *(const float4*)(bias + hcg);
    const float4 bz = *(const float4*)(bias + 256 + hcg);
    const float4 bn = *(const float4*)(bias + 512 + hcg);
    const float4 wvA = *(const float4*)(attn_w + (isf?0:256) + hcg);
    const float4 wvB = *(const float4*)(attn_w + 256 + hcg);

    float* bA0 = g_hA + (size_t)slotA*(B_*H_);
    float* bA1 = g_hB + (size_t)slotA*(B_*H_);
    float* bB0 = g_hA + (size_t)(iB < 0 ? 0 : iB)*(B_*H_);
    float* bB1 = g_hB + (size_t)(iB < 0 ? 0 : iB)*(B_*H_);

    const int srow = tid >> 3, skb = (tid & 7)*4;
    __syncthreads();

    for (int s = 0; s < lenA; s++) {
        float* hsrcA = (s&1) ? bA1 : bA0;  float* hdstA = (s&1) ? bA0 : bA1;
        float* hsrcB = (s&1) ? bB1 : bB0;  float* hdstB = (s&1) ? bB0 : bB1;
        const bool actB = !isf && (s < lenB);
        {
            const float* src = hsrcA + srow*256 + skb;
            float* d = HSA + srow*HSTR + skb;
#pragma unroll
            for (int q = 0; q < 8; q++) *(float4*)(d+q*32) = __ldcg((const float4*)(src+q*32));
            if (actB) {
                const float* sb = hsrcB + srow*256 + skb;
                float* db = HSB + srow*HSTR + skb;
#pragma unroll
                for (int q = 0; q < 8; q++) *(float4*)(db+q*32) = __ldcg((const float4*)(sb+q*32));
            }
        }
        __syncthreads();

        const float* giA = (isf ? (g_gif + (size_t)s*(B_*G_))
                                : (g_gir + (size_t)(iA-s)*(B_*G_))) + (size_t)lane*G_ + hcg;
        float4 grA = *(const float4*)giA;
        float4 gzA = *(const float4*)(giA+256);
        float4 gnA = *(const float4*)(giA+512);
        float4 grB, gzB, gnB;
        if (actB) {
            const float* giB = g_gir + (size_t)(iB-s)*(B_*G_) + (size_t)lane*G_ + hcg;
            grB = *(const float4*)giB; gzB = *(const float4*)(giB+256); gnB = *(const float4*)(giB+512);
        }

        ull aA[6] = {0,0,0,0,0,0}, aB[6] = {0,0,0,0,0,0};
        const float* wk = WS + hc;
        const float* hkA = HSA + lane*HSTR;
        const float* hkB = HSB + lane*HSTR;
        if (!isf) {
#pragma unroll 4
            for (int kq = 0; kq < 64; kq++) {
                float4 hA4 = *(const float4*)(hkA + kq*4);
                float4 hB4 = *(const float4*)(hkB + kq*4);
                const float* fA = (const float*)&hA4;
                const float* fB = (const float*)&hB4;
#pragma unroll
                for (int j = 0; j < 4; j++) {
                    const float* wp = wk + (kq*4+j)*96;
                    ulonglong2 rr = *(const ulonglong2*)(wp);
                    ulonglong2 zz = *(const ulonglong2*)(wp+32);
                    ulonglong2 nn = *(const ulonglong2*)(wp+64);
                    ull avA = splat2(fA[j]), avB = splat2(fB[j]);
                    fma2(aA[0],avA,rr.x); fma2(aA[1],avA,rr.y);
                    fma2(aA[2],avA,zz.x); fma2(aA[3],avA,zz.y);
                    fma2(aA[4],avA,nn.x); fma2(aA[5],avA,nn.y);
                    fma2(aB[0],avB,rr.x); fma2(aB[1],avB,rr.y);
                    fma2(aB[2],avB,zz.x); fma2(aB[3],avB,zz.y);
                    fma2(aB[4],avB,nn.x); fma2(aB[5],avB,nn.y);
                }
            }
        } else {
#pragma unroll 4
            for (int kq = 0; kq < 64; kq++) {
                float4 hA4 = *(const float4*)(hkA + kq*4);
                const float* fA = (const float*)&hA4;
#pragma unroll
                for (int j = 0; j < 4; j++) {
                    const float* wp = wk + (kq*4+j)*96;
                    ulonglong2 rr = *(const ulonglong2*)(wp);
                    ulonglong2 zz = *(const ulonglong2*)(wp+32);
                    ulonglong2 nn = *(const ulonglong2*)(wp+64);
                    ull avA = splat2(fA[j]);
                    fma2(aA[0],avA,rr.x); fma2(aA[1],avA,rr.y);
                    fma2(aA[2],avA,zz.x); fma2(aA[3],avA,zz.y);
                    fma2(aA[4],avA,nn.x); fma2(aA[5],avA,nn.y);
                }
            }
        }

        // pointwise A
        {
            float2 r01=unpack2(aA[0]), r23=unpack2(aA[1]);
            float2 z01=unpack2(aA[2]), z23=unpack2(aA[3]);
            float2 n01=unpack2(aA[4]), n23=unpack2(aA[5]);
            const float* hp_ = hkA + hcg;
            float r0=sigm(grA.x+r01.x+br.x), r1=sigm(grA.y+r01.y+br.y);
            float r2=sigm(grA.z+r23.x+br.z), r3=sigm(grA.w+r23.y+br.w);
            float z0=sigm(gzA.x+z01.x+bz.x), z1=sigm(gzA.y+z01.y+bz.y);
            float z2=sigm(gzA.z+z23.x+bz.z), z3=sigm(gzA.w+z23.y+bz.w);
            float n0=tanh_(gnA.x+r0*(n01.x+bn.x)), n1=tanh_(gnA.y+r1*(n01.y+bn.y));
            float n2=tanh_(gnA.z+r2*(n23.x+bn.z)), n3=tanh_(gnA.w+r3*(n23.y+bn.w));
            float4 hv;
            hv.x=(1.f-z0)*n0+z0*hp_[0]; hv.y=(1.f-z1)*n1+z1*hp_[1];
            hv.z=(1.f-z2)*n2+z2*hp_[2]; hv.w=(1.f-z3)*n3+z3*hp_[3];
            __stcg((float4*)(hdstA + lane*256 + hcg), hv);
            float* outp = isf ? (g_fwd + (size_t)s*(B_*H_))
                              : (g_rev + ((size_t)iA*64 + s)*(B_*H_));
            *(float4*)(outp + lane*256 + hcg) = hv;
            SBA[w*32+lane] = hv.x*wvA.x + hv.y*wvA.y + hv.z*wvA.z + hv.w*wvA.w;
        }
        // pointwise B
        if (actB) {
            float2 r01=unpack2(aB[0]), r23=unpack2(aB[1]);
            float2 z01=unpack2(aB[2]), z23=unpack2(aB[3]);
            float2 n01=unpack2(aB[4]), n23=unpack2(aB[5]);
            const float* hp_ = hkB + hcg;
            float r0=sigm(grB.x+r01.x+br.x), r1=sigm(grB.y+r01.y+br.y);
            float r2=sigm(grB.z+r23.x+br.z), r3=sigm(grB.w+r23.y+br.w);
            float z0=sigm(gzB.x+z01.x+bz.x), z1=sigm(gzB.y+z01.y+bz.y);
            float z2=sigm(gzB.z+z23.x+bz.z), z3=sigm(gzB.w+z23.y+bz.w);
            float n0=tanh_(gnB.x+r0*(n01.x+bn.x)), n1=tanh_(gnB.y+r1*(n01.y+bn.y));
            float n2=tanh_(gnB.z+r2*(n23.x+bn.z)), n3=tanh_(gnB.w+r3*(n23.y+bn.w));
            float4 hv;
            hv.x=(1.f-z0)*n0+z0*hp_[0]; hv.y=(1.f-z1)*n1+z1*hp_[1];
            hv.z=(1.f-z2)*n2+z2*hp_[2]; hv.w=(1.f-z3)*n3+z3*hp_[3];
            __stcg((float4*)(hdstB + lane*256 + hcg), hv);
            *(float4*)(g_rev + ((size_t)iB*64 + s)*(B_*H_) + lane*256 + hcg) = hv;
            SBB[w*32+lane] = hv.x*wvB.x + hv.y*wvB.y + hv.z*wvB.z + hv.w*wvB.w;
        }
        __syncthreads();
        if (w == 0) {
            float v = 0.f;
#pragma unroll
            for (int q = 0; q < 8; q++) v += SBA[q*32+lane];
            if (isf) g_scfp[(chunk*64+s)*32+lane] = v;
            else     g_scrp[(((size_t)chunk*64+iA)*64+s)*32+lane] = v;
        } else if (w == 1 && actB) {
            float v = 0.f;
#pragma unroll
            for (int q = 0; q < 8; q++) v += SBB[q*32+lane];
            g_scrp[(((size_t)chunk*64+iB)*64+s)*32+lane] = v;
        }
        if (s != lenA-1) {
            asm volatile("barrier.cluster.arrive.aligned;" ::: "memory");
            asm volatile("barrier.cluster.wait.aligned;"   ::: "memory");
        }
    }
}

__global__ __launch_bounds__(256) void combine_softmax(const float* __restrict__ attn_b) {
    const int i = blockIdx.x;
    __shared__ float sc[T_*B_];
    const float ab = attn_b[0];
    for (int idx = threadIdx.x; idx < (i+1)*32; idx += 256) {
        int t = idx >> 5, b = idx & 31;
        float v = ab;
#pragma unroll
        for (int c = 0; c < 8; c++) {
            v += g_scrp[(((size_t)c*64+i)*64+t)*32+b];
            v += g_scfp[(c*64+t)*32+b];
        }
        sc[t*32+b] = v;
    }
    __syncthreads();
    if (threadIdx.x < 32) {
        const int b = threadIdx.x;
        float m = -1e30f;
        for (int t = 0; t <= i; t++) m = fmaxf(m, sc[t*32+b]);
        float ssum = 0.f;
        for (int t = 0; t <= i; t++) {
            float e = ex2f_(1.4426950408889634f*(sc[t*32+b]-m));
            sc[t*32+b] = e; ssum += e;
        }
        float inv = 1.f/ssum;
        for (int t = 0; t <= i; t++) g_sc[(i*64+t)*32+b] = sc[t*32+b]*inv;
    }
}

__global__ __launch_bounds__(256) void context_k() {
    const int i = blockIdx.x, bg = blockIdx.y;
    const int h = threadIdx.x;
    float accf[8], accr[8];
#pragma unroll
    for (int j = 0; j < 8; j++) { accf[j]=0.f; accr[j]=0.f; }
    for (int t = 0; t <= i; t++) {
        const float* al = g_sc + (i*64+t)*32 + bg*8;
        const float* fr = g_fwd + ((size_t)(t*32+bg*8))*256 + h;
        const float* rr = g_rev + ((size_t)((i*64+t)*32+bg*8))*256 + h;
#pragma unroll
        for (int j = 0; j < 8; j++) {
            float a = al[j];
            accf[j] += a*fr[(size_t)j*256];
            accr[j] += a*rr[(size_t)j*256];
        }
    }
    float inv = 1.f/(float)(i+1);
#pragma unroll
    for (int j = 0; j < 8; j++) {
        int b = bg*8+j;
        size_t row = (size_t)(i*32+b);
        g_ht[row*1024 + h]       = accf[j]*inv;
        g_ht[row*1024 + 256 + h] = accr[j]*inv;
        g_ht[row*1024 + 512 + h] = g_fwd[((size_t)(i*32+b))*256 + h];
        g_ht[row*1024 + 768 + h] = g_rev[((size_t)((i*64+i)*32+b))*256 + h];
    }
}

extern "C" void kernel_launch(void* const* d_in, const int* in_sizes, int n_in,
                              void* d_out, int out_size)
{
    const float* x      = (const float*)d_in[0];
    const float* W_emb  = (const float*)d_in[1];
    const float* b_emb  = (const float*)d_in[2];
    const float* Wih_f  = (const float*)d_in[3];
    const float* Whh_f  = (const float*)d_in[4];
    const float* bih_f  = (const float*)d_in[5];
    const float* bhh_f  = (const float*)d_in[6];
    const float* Wih_r  = (const float*)d_in[7];
    const float* Whh_r  = (const float*)d_in[8];
    const float* bih_r  = (const float*)d_in[9];
    const float* bhh_r  = (const float*)d_in[10];
    const float* attn_w = (const float*)d_in[11];
    const float* attn_b = (const float*)d_in[12];
    const float* W_ao   = (const float*)d_in[13];
    const float* b_ao   = (const float*)d_in[14];
    const float* W_o    = (const float*)d_in[15];
    const float* b_o    = (const float*)d_in[16];
    float* out = (float*)d_out;

    void *p_day, *p_ht, *p_hto;
    cudaGetSymbolAddress(&p_day, g_day);
    cudaGetSymbolAddress(&p_ht,  g_ht);
    cudaGetSymbolAddress(&p_hto, g_hto);

    const int RNN_SMEM = (24576 + 2*32*HSTR + 512) * 4;  // 166912 B
    cudaFuncSetAttribute(chain_rnn, cudaFuncAttributeMaxDynamicSharedMemorySize, RNN_SMEM);

    zero_k<<<512, 256>>>();                                                   // 0
    gemm_v3<false><<<dim3(4, 32), 256>>>(x, W_emb, b_emb, (float*)p_day, DD_, DIN_);  // 1
    gi_fused<<<dim3(12, 32, 2), 256>>>(Wih_f, bih_f, Wih_r, bih_r);           // 2
    chain_rnn<<<264, 256, RNN_SMEM>>>(Whh_f, Whh_r, bhh_f, bhh_r, attn_w);    // 3 (profiled)
    combine_softmax<<<64, 256>>>(attn_b);                                     // 4
    context_k<<<dim3(64, 4), 256>>>();                                        // 5
    gemm_v3<false><<<dim3(4, 32), 256>>>((const float*)p_ht, W_ao, b_ao, (float*)p_hto, DD_, 4*H_); // 6
    gemm_v3<true><<<dim3(15, 32), 256>>>((const float*)p_hto, W_o, b_o, out, DOUT_, DD_);           // 7
}